// round 14
// baseline (speedup 1.0000x reference)
#include <cuda_runtime.h>
#include <cuda_fp16.h>
#include <cstdint>

#define DIM      2048
#define KVDIM    512
#define QKVN     (DIM + 2 * KVDIM)   // 3072
#define SEQ      2048
#define BATCH    2
#define NHEADS   32
#define HD       64
#define ROWS     (BATCH * SEQ)   // 4096

// -------- static scratch (no allocations allowed) --------
__device__ __half g_x[ROWS * DIM];                       // x fp16
__device__ __half g_Wqkv[DIM * QKVN];                    // [2048][3072] fp16
__device__ __half g_Wo[DIM * DIM];                       // [2048][2048] fp16
__device__ __half g_Q[ROWS * DIM];                       // pre-scaled fp16 (0.125*log2e)
__device__ __half g_K[ROWS * KVDIM], g_V[ROWS * KVDIM];  // fp16
__device__ __half g_O[ROWS * DIM];                       // attn out fp16

// ============================================================================
// helpers
// ============================================================================
__device__ __forceinline__ uint32_t smem_u32(const void* p) {
    return (uint32_t)__cvta_generic_to_shared(p);
}
__device__ __forceinline__ void ldsm_x4(uint32_t* r, uint32_t addr) {
    asm volatile("ldmatrix.sync.aligned.m8n8.x4.shared.b16 {%0,%1,%2,%3}, [%4];"
                 : "=r"(r[0]), "=r"(r[1]), "=r"(r[2]), "=r"(r[3]) : "r"(addr));
}
__device__ __forceinline__ void ldsm_x4t(uint32_t* r, uint32_t addr) {
    asm volatile("ldmatrix.sync.aligned.m8n8.x4.trans.shared.b16 {%0,%1,%2,%3}, [%4];"
                 : "=r"(r[0]), "=r"(r[1]), "=r"(r[2]), "=r"(r[3]) : "r"(addr));
}
__device__ __forceinline__ void ldsm_x2t(uint32_t* r, uint32_t addr) {
    asm volatile("ldmatrix.sync.aligned.m8n8.x2.trans.shared.b16 {%0,%1}, [%2];"
                 : "=r"(r[0]), "=r"(r[1]) : "r"(addr));
}
__device__ __forceinline__ void mma_h(float* c, const uint32_t* a, const uint32_t* b) {
    asm volatile(
        "mma.sync.aligned.m16n8k16.row.col.f32.f16.f16.f32 "
        "{%0,%1,%2,%3}, {%4,%5,%6,%7}, {%8,%9}, {%0,%1,%2,%3};"
        : "+f"(c[0]), "+f"(c[1]), "+f"(c[2]), "+f"(c[3])
        : "r"(a[0]), "r"(a[1]), "r"(a[2]), "r"(a[3]), "r"(b[0]), "r"(b[1]));
}
// fp16-accumulator mma: C/D are 2 b32 regs (4 halfs)
__device__ __forceinline__ void mma_h16(uint32_t* c, const uint32_t* a, const uint32_t* b) {
    asm volatile(
        "mma.sync.aligned.m16n8k16.row.col.f16.f16.f16.f16 "
        "{%0,%1}, {%2,%3,%4,%5}, {%6,%7}, {%0,%1};"
        : "+r"(c[0]), "+r"(c[1])
        : "r"(a[0]), "r"(a[1]), "r"(a[2]), "r"(a[3]), "r"(b[0]), "r"(b[1]));
}
__device__ __forceinline__ uint32_t ex2_f16x2(uint32_t x) {
    uint32_t d;
    asm("ex2.approx.f16x2 %0, %1;" : "=r"(d) : "r"(x));
    return d;
}
__device__ __forceinline__ void cp16(uint32_t dst, const void* src) {
    asm volatile("cp.async.cg.shared.global [%0], [%1], 16;" :: "r"(dst), "l"(src));
}
__device__ __forceinline__ void cp_commit() { asm volatile("cp.async.commit_group;"); }
__device__ __forceinline__ void cp_wait0()  { asm volatile("cp.async.wait_group 0;"); }
__device__ __forceinline__ void cp_wait1()  { asm volatile("cp.async.wait_group 1;"); }

__device__ __forceinline__ uint32_t packh(float a, float b) {
    __half2 t = __floats2half2_rn(a, b);
    return *reinterpret_cast<uint32_t*>(&t);
}

#define SW128(off) ((off) ^ (((off) >> 3) & 0x70))
// Q scale includes log2(e) for exp2-domain softmax downstream.
#define QSCALE  (0.125f * 1.4426950408889634f)

// ============================================================================
// fused pre-pass: convert x, Wq|Wk|Wv (packed), Wo to fp16 in ONE launch.
// MLP=4: each thread handles 4 widely-spaced float4s (independent loads).
// ============================================================================
#define N4_X   (ROWS * DIM / 4)
#define N4_WQ  (DIM * DIM / 4)
#define N4_WK  (DIM * KVDIM / 4)
#define N4_WV  (DIM * KVDIM / 4)
#define N4_WO  (DIM * DIM / 4)
#define N4_TOT (N4_X + N4_WQ + N4_WK + N4_WV + N4_WO)   // 4718592
#define N4_Q   (N4_TOT / 4)                              // 1179648

__global__ __launch_bounds__(256) void conv_all(
    const float4* __restrict__ x,  const float4* __restrict__ Wq,
    const float4* __restrict__ Wk, const float4* __restrict__ Wv,
    const float4* __restrict__ Wo,
    __half* __restrict__ dx, __half* __restrict__ dqkv, __half* __restrict__ dwo)
{
    int idx = blockIdx.x * 256 + threadIdx.x;
    if (idx >= N4_Q) return;

    float4 v[4];
    __half* dptr[4];
    #pragma unroll
    for (int k = 0; k < 4; k++) {
        int i = idx + k * N4_Q;
        const float4* src;
        __half* dst;
        int li, N4, dstride, coloff;
        if (i < N4_X) {
            src = x;  dst = dx;  li = i;
            N4 = DIM / 4;  dstride = DIM;  coloff = 0;
        } else if (i < N4_X + N4_WQ) {
            src = Wq; dst = dqkv; li = i - N4_X;
            N4 = DIM / 4;  dstride = QKVN; coloff = 0;
        } else if (i < N4_X + N4_WQ + N4_WK) {
            src = Wk; dst = dqkv; li = i - (N4_X + N4_WQ);
            N4 = KVDIM / 4; dstride = QKVN; coloff = DIM;
        } else if (i < N4_X + N4_WQ + N4_WK + N4_WV) {
            src = Wv; dst = dqkv; li = i - (N4_X + N4_WQ + N4_WK);
            N4 = KVDIM / 4; dstride = QKVN; coloff = DIM + KVDIM;
        } else {
            src = Wo; dst = dwo; li = i - (N4_X + N4_WQ + N4_WK + N4_WV);
            N4 = DIM / 4;  dstride = DIM;  coloff = 0;
        }
        int row = li / N4, c4 = li % N4;
        dptr[k] = dst + (long)row * dstride + coloff + c4 * 4;
        v[k] = src[li];   // 4 independent loads in flight
    }
    #pragma unroll
    for (int k = 0; k < 4; k++) {
        uint2 hh;
        hh.x = packh(v[k].x, v[k].y);
        hh.y = packh(v[k].z, v[k].w);
        *reinterpret_cast<uint2*>(dptr[k]) = hh;
    }
}

// ============================================================================
// fp16 single-product GEMM: C = A * B.  K = 2048 fixed.
// Block tile 128x128, *** BK=64 ***, 128 threads (4 warps 2x2), warp 64x64.
// A smem: 128 rows x 64 halfs (128B rows), SW128 swizzle (16 KB).
// B smem: 64 rows x 136 halfs padded (17408 B).
// 3-stage cp.async pipeline (101 KB), wait_group 1.  2 CTAs/SM.
// 32 mainloop iterations (half the barriers of BK=32).
// EPI: 0 = fp32 out0 ; 1 = fused QKV (q scaled fp16 / k fp16 / v fp16)
// ============================================================================
#define GK      2048
#define G_BK    64
#define G_NK    (GK / G_BK)        // 32
#define G_AB    16384
#define G_BB    17408
#define G_ST    (G_AB + G_BB)      // 33792
#define G_SMEM  (3 * G_ST)         // 101376
#define GBSTR   136

template<int EPI>
__global__ __launch_bounds__(128, 2) void gemm_fp16(
    int Bstride,
    const __half* __restrict__ A,
    const __half* __restrict__ B,
    void* __restrict__ out0, void* __restrict__ out1, void* __restrict__ out2)
{
    extern __shared__ __align__(16) char gsm[];
    const uint32_t sbase = smem_u32(gsm);

    const int tid  = threadIdx.x;
    const int lane = tid & 31;
    const int warp = tid >> 5;        // 0..3
    const int wm   = warp >> 1;       // 0..1
    const int wn   = warp & 1;        // 0..1
    const long M0  = (long)blockIdx.y * 128;
    const long N0  = (long)blockIdx.x * 128;

    float c[4][8][4];
    #pragma unroll
    for (int i = 0; i < 4; i++)
        #pragma unroll
        for (int j = 0; j < 8; j++)
            #pragma unroll
            for (int e = 0; e < 4; e++) c[i][j][e] = 0.0f;

    auto loadStage = [&](int st, int k0) {
        uint32_t sA = sbase + st * G_ST;
        uint32_t sB = sA + G_AB;
        // A: 128 rows x 8 chunks of 16B (64 halfs/row)
        #pragma unroll
        for (int i = 0; i < 8; i++) {
            int ci = tid + i * 128;
            int row = ci >> 3, ch = ci & 7;
            uint32_t so = SW128((uint32_t)(row * 128 + ch * 16));
            long go = (M0 + row) * (long)GK + k0 + ch * 8;
            cp16(sA + so, A + go);
        }
        // B: 64 rows x 16 chunks of 8 halfs
        #pragma unroll
        for (int i = 0; i < 8; i++) {
            int ci = tid + i * 128;
            int row = ci >> 4, c8 = ci & 15;
            uint32_t so = (uint32_t)(row * GBSTR + c8 * 8) * 2;
            long go = (long)(k0 + row) * Bstride + N0 + c8 * 8;
            cp16(sB + so, B + go);
        }
    };

    loadStage(0, 0);
    cp_commit();
    loadStage(1, G_BK);
    cp_commit();

    #pragma unroll 1
    for (int kt = 0; kt < G_NK; kt++) {
        if (kt + 1 < G_NK) cp_wait1(); else cp_wait0();
        __syncthreads();
        if (kt + 2 < G_NK) {
            loadStage((kt + 2) % 3, (kt + 2) * G_BK);
            cp_commit();
        }

        const uint32_t sA = sbase + (kt % 3) * G_ST;
        const uint32_t sB = sA + G_AB;

        #pragma unroll
        for (int kk = 0; kk < G_BK; kk += 16) {
            uint32_t ah[4][4], bb[4][4];
            #pragma unroll
            for (int i = 0; i < 4; i++) {
                int row = wm * 64 + i * 16 + (lane & 15);
                int colb = (kk + ((lane >> 4) << 3)) * 2;
                uint32_t off = SW128((uint32_t)(row * 128 + colb));
                ldsm_x4(ah[i], sA + off);
            }
            #pragma unroll
            for (int jp = 0; jp < 4; jp++) {
                int row = kk + (lane & 15);
                int col = wn * 64 + jp * 16 + ((lane >> 4) << 3);
                uint32_t off = (uint32_t)(row * GBSTR + col) * 2;
                ldsm_x4t(bb[jp], sB + off);
            }
            #pragma unroll
            for (int i = 0; i < 4; i++)
                #pragma unroll
                for (int jp = 0; jp < 4; jp++) {
                    mma_h(c[i][2 * jp],     ah[i], bb[jp]);
                    mma_h(c[i][2 * jp + 1], ah[i], bb[jp] + 2);
                }
        }
    }

    // ---- epilogue ----
    float scale = 1.0f;
    __half* dsth = nullptr;
    long dstride = 0, col0 = 0;
    if (EPI == 1) {
        if (N0 < DIM)              { dsth = (__half*)out0; dstride = DIM;   col0 = N0;               scale = QSCALE; }
        else if (N0 < DIM + KVDIM) { dsth = (__half*)out1; dstride = KVDIM; col0 = N0 - DIM;         }
        else                       { dsth = (__half*)out2; dstride = KVDIM; col0 = N0 - DIM - KVDIM; }
    }

    #pragma unroll
    for (int i = 0; i < 4; i++) {
        long r0 = M0 + wm * 64 + i * 16 + (lane >> 2);
        #pragma unroll
        for (int j = 0; j < 8; j++) {
            long cc = wn * 64 + j * 8 + 2 * (lane & 3);
            float v0 = c[i][j][0] * scale, v1 = c[i][j][1] * scale;
            float v2 = c[i][j][2] * scale, v3 = c[i][j][3] * scale;
            if (EPI == 0) {
                float* C = (float*)out0;
                *reinterpret_cast<float2*>(&C[r0 * DIM + N0 + cc])       = make_float2(v0, v1);
                *reinterpret_cast<float2*>(&C[(r0 + 8) * DIM + N0 + cc]) = make_float2(v2, v3);
            } else {
                *reinterpret_cast<uint32_t*>(&dsth[r0 * dstride + col0 + cc])       = packh(v0, v1);
                *reinterpret_cast<uint32_t*>(&dsth[(r0 + 8) * dstride + col0 + cc]) = packh(v2, v3);
            }
        }
    }
}

// ============================================================================
// fp16 flash attention — fp16 S/P datapath (unchanged from R13).
// 4 warps, 32 q-rows/warp, KT=64, double-buffered cp.async, 2 CTAs/SM.
// ============================================================================
#define TSTR 72
#define Q_BYTES  (128 * TSTR * 2)              // 18432
#define KV_BYTES (64 * TSTR * 2)               //  9216
#define A_STAGE  (2 * KV_BYTES)
#define ATTN_SMEM (Q_BYTES + 2 * A_STAGE)      // 55296

__global__ __launch_bounds__(128, 2) void attn_fp16(
    const __half* __restrict__ Q_g,
    const __half* __restrict__ K_g,  const __half* __restrict__ V_g,
    __half* __restrict__ O_g)
{
    extern __shared__ __align__(16) char smp[];
    const uint32_t sb  = smem_u32(smp);
    const uint32_t sQ  = sb;
    const uint32_t sKV = sb + Q_BYTES;

    const int tid  = threadIdx.x;
    const int lane = tid & 31;
    const int warp = tid >> 5;
    const int qt = blockIdx.x, h = blockIdx.y, b = blockIdx.z;
    const int kvh = h >> 2;

    // ---- init V padding cols 64..71 = {1,0,...} for BOTH stages ----
    {
        int st = tid >> 6, row = tid & 63;
        char* p = smp + (size_t)(Q_BYTES + st * A_STAGE + KV_BYTES) +
                  (size_t)(row * TSTR + 64) * 2;
        *reinterpret_cast<uint4*>(p) = make_uint4(0x00003C00u, 0u, 0u, 0u);
    }

    auto loadKV = [&](int st, int kt) {
        uint32_t sK = sKV + st * A_STAGE;
        uint32_t sV = sK + KV_BYTES;
        #pragma unroll
        for (int i = 0; i < 4; i++) {
            int ci = tid + i * 128;
            int row = ci >> 3, c8 = ci & 7;
            uint32_t so = (uint32_t)(row * TSTR + c8 * 8) * 2;
            long go = (long)(b * SEQ + kt * 64 + row) * KVDIM + kvh * HD + c8 * 8;
            cp16(sK + so, K_g + go);
            cp16(sV + so, V_g + go);
        }
    };

    #pragma unroll
    for (int i = 0; i < 8; i++) {
        int ci = tid + i * 128;
        int row = ci >> 3, c8 = ci & 7;
        uint32_t so = (uint32_t)(row * TSTR + c8 * 8) * 2;
        long go = (long)(b * SEQ + qt * 128 + row) * DIM + h * HD + c8 * 8;
        cp16(sQ + so, Q_g + go);
    }
    loadKV(0, 0);
    cp_commit();
    cp_wait0();
    __syncthreads();

    uint32_t qh[2][4][4];
    #pragma unroll
    for (int rt = 0; rt < 2; rt++)
        #pragma unroll
        for (int t = 0; t < 4; t++) {
            int row = warp * 32 + rt * 16 + (lane & 15);
            int col = t * 16 + (lane >> 4) * 8;
            ldsm_x4(qh[rt][t], sQ + (uint32_t)(row * TSTR + col) * 2);
        }

    float o[2][8][4];
    #pragma unroll
    for (int rt = 0; rt < 2; rt++)
        #pragma unroll
        for (int j = 0; j < 8; j++)
            #pragma unroll
            for (int e = 0; e < 4; e++) o[rt][j][e] = 0.0f;
    float ol[2][4];
    #pragma unroll
    for (int rt = 0; rt < 2; rt++)
        #pragma unroll
        for (int e = 0; e < 4; e++) ol[rt][e] = 0.0f;

    for (int kt = 0; kt < SEQ / 64; kt++) {
        const int cur = kt & 1;
        if (kt + 1 < SEQ / 64) { loadKV(cur ^ 1, kt + 1); }
        cp_commit();

        const uint32_t sK = sKV + cur * A_STAGE;
        const uint32_t sV = sK + KV_BYTES;

        uint32_t s16[2][8][2];
        #pragma unroll
        for (int rt = 0; rt < 2; rt++)
            #pragma unroll
            for (int j = 0; j < 8; j++) { s16[rt][j][0] = 0u; s16[rt][j][1] = 0u; }

        const int l7 = lane & 7, g4 = lane >> 3;
        #pragma unroll
        for (int t = 0; t < 4; t++) {
            #pragma unroll
            for (int jp = 0; jp < 4; jp++) {
                uint32_t kb[4];
                int row = jp * 16 + ((g4 >> 1) << 3) + l7;
                int col = t * 16 + ((g4 & 1) << 3);
                ldsm_x4(kb, sK + (uint32_t)(row * TSTR + col) * 2);
                #pragma unroll
                for (int rt = 0; rt < 2; rt++) {
                    mma_h16(s16[rt][2 * jp],     qh[rt][t], kb);
                    mma_h16(s16[rt][2 * jp + 1], qh[rt][t], kb + 2);
                }
            }
        }

        #pragma unroll
        for (int rt = 0; rt < 2; rt++)
            #pragma unroll
            for (int j = 0; j < 8; j++) {
                s16[rt][j][0] = ex2_f16x2(s16[rt][j][0]);
                s16[rt][j][1] = ex2_f16x2(s16[rt][j][1]);
            }

        #pragma unroll
        for (int t = 0; t < 4; t++) {
            uint32_t ph[2][4];
            #pragma unroll
            for (int rt = 0; rt < 2; rt++) {
                ph[rt][0] = s16[rt][2 * t][0];
                ph[rt][1] = s16[rt][2 * t][1];
                ph[rt][2] = s16[rt][2 * t + 1][0];
                ph[rt][3] = s16[rt][2 * t + 1][1];
            }
            #pragma unroll
            for (int jp = 0; jp < 4; jp++) {
                uint32_t vb[4];
                int row = t * 16 + (lane & 15);
                int col = jp * 16 + ((lane >> 4) << 3);
                ldsm_x4t(vb, sV + (uint32_t)(row * TSTR + col) * 2);
                #pragma unroll
                for (int rt = 0; rt < 2; rt++) {
                    mma_h(o[rt][2 * jp],     ph[rt], vb);
                    mma_h(o[rt][2 * jp + 1], ph[rt], vb + 2);
                }
            }
            {
                uint32_t vb1[2];
                int row = t * 16 + (lane & 15);
                ldsm_x2t(vb1, sV + (uint32_t)(row * TSTR + 64) * 2);
                #pragma unroll
                for (int rt = 0; rt < 2; rt++)
                    mma_h(ol[rt], ph[rt], vb1);
            }
        }

        if (kt + 1 < SEQ / 64) cp_wait0();
        __syncthreads();
    }

    #pragma unroll
    for (int rt = 0; rt < 2; rt++) {
        float lv0 = __shfl_sync(0xffffffffu, ol[rt][0], lane & 0x1C);
        float lv1 = __shfl_sync(0xffffffffu, ol[rt][2], lane & 0x1C);
        const float il0 = 1.0f / lv0, il1 = 1.0f / lv1;
        const long base = (long)(b * SEQ + qt * 128 + warp * 32 + rt * 16 +
                                 (lane >> 2)) * DIM + h * HD;
        #pragma unroll
        for (int j = 0; j < 8; j++) {
            const int col = j * 8 + 2 * (lane & 3);
            *reinterpret_cast<uint32_t*>(&O_g[base + col]) =
                packh(o[rt][j][0] * il0, o[rt][j][1] * il0);
            *reinterpret_cast<uint32_t*>(&O_g[base + 8L * DIM + col]) =
                packh(o[rt][j][2] * il1, o[rt][j][3] * il1);
        }
    }
}

// ============================================================================
// kernel_launch
// ============================================================================
extern "C" void kernel_launch(void* const* d_in, const int* in_sizes, int n_in,
                              void* d_out, int out_size)
{
    const float* x  = (const float*)d_in[0];
    const float* Wq = (const float*)d_in[1];
    const float* Wk = (const float*)d_in[2];
    const float* Wv = (const float*)d_in[3];
    const float* Wo = (const float*)d_in[4];
    float* out = (float*)d_out;

    void *px, *pwqkv, *pwo, *pQ, *pK, *pV, *pO;
    cudaGetSymbolAddress(&px, g_x);
    cudaGetSymbolAddress(&pwqkv, g_Wqkv); cudaGetSymbolAddress(&pwo, g_Wo);
    cudaGetSymbolAddress(&pQ, g_Q);
    cudaGetSymbolAddress(&pK, g_K);       cudaGetSymbolAddress(&pV, g_V);
    cudaGetSymbolAddress(&pO, g_O);

    cudaFuncSetAttribute((const void*)gemm_fp16<0>,
                         cudaFuncAttributeMaxDynamicSharedMemorySize, G_SMEM);
    cudaFuncSetAttribute((const void*)gemm_fp16<1>,
                         cudaFuncAttributeMaxDynamicSharedMemorySize, G_SMEM);
    cudaFuncSetAttribute((const void*)attn_fp16,
                         cudaFuncAttributeMaxDynamicSharedMemorySize, ATTN_SMEM);

    // fused pre-pass (one launch, MLP=4)
    conv_all<<<(N4_Q + 255) / 256, 256>>>(
        (const float4*)x, (const float4*)Wq, (const float4*)Wk,
        (const float4*)Wv, (const float4*)Wo,
        (__half*)px, (__half*)pwqkv, (__half*)pwo);

    // fused QKV projection: [4096,2048] x [2048,3072]
    gemm_fp16<1><<<dim3(QKVN / 128, ROWS / 128), 128, G_SMEM>>>(
        QKVN, (__half*)px, (__half*)pwqkv, pQ, pK, pV);
    // attention -> fp16
    attn_fp16<<<dim3(SEQ / 128, NHEADS, BATCH), 128, ATTN_SMEM>>>(
        (const __half*)pQ, (const __half*)pK, (const __half*)pV, (__half*)pO);
    // out = O @ Wo -> fp32
    gemm_fp16<0><<<dim3(DIM / 128, ROWS / 128), 128, G_SMEM>>>(
        DIM, (__half*)pO, (__half*)pwo, out, nullptr, nullptr);
}

// round 15
// speedup vs baseline: 1.0747x; 1.0747x over previous
#include <cuda_runtime.h>
#include <cuda_fp16.h>
#include <cstdint>

#define DIM      2048
#define KVDIM    512
#define QKVN     (DIM + 2 * KVDIM)   // 3072
#define SEQ      2048
#define BATCH    2
#define NHEADS   32
#define HD       64
#define ROWS     (BATCH * SEQ)   // 4096

// -------- static scratch (no allocations allowed) --------
__device__ __half g_x[ROWS * DIM];                       // x fp16
__device__ __half g_Wqkv[DIM * QKVN];                    // [2048][3072] fp16
__device__ __half g_Wo[DIM * DIM];                       // [2048][2048] fp16
__device__ __half g_Q[ROWS * DIM];                       // pre-scaled fp16 (0.125*log2e)
__device__ __half g_K[ROWS * KVDIM], g_V[ROWS * KVDIM];  // fp16
__device__ __half g_O[ROWS * DIM];                       // attn out fp16

// ============================================================================
// helpers
// ============================================================================
__device__ __forceinline__ uint32_t smem_u32(const void* p) {
    return (uint32_t)__cvta_generic_to_shared(p);
}
__device__ __forceinline__ void ldsm_x4(uint32_t* r, uint32_t addr) {
    asm volatile("ldmatrix.sync.aligned.m8n8.x4.shared.b16 {%0,%1,%2,%3}, [%4];"
                 : "=r"(r[0]), "=r"(r[1]), "=r"(r[2]), "=r"(r[3]) : "r"(addr));
}
__device__ __forceinline__ void ldsm_x4t(uint32_t* r, uint32_t addr) {
    asm volatile("ldmatrix.sync.aligned.m8n8.x4.trans.shared.b16 {%0,%1,%2,%3}, [%4];"
                 : "=r"(r[0]), "=r"(r[1]), "=r"(r[2]), "=r"(r[3]) : "r"(addr));
}
__device__ __forceinline__ void ldsm_x2t(uint32_t* r, uint32_t addr) {
    asm volatile("ldmatrix.sync.aligned.m8n8.x2.trans.shared.b16 {%0,%1}, [%2];"
                 : "=r"(r[0]), "=r"(r[1]) : "r"(addr));
}
__device__ __forceinline__ void mma_h(float* c, const uint32_t* a, const uint32_t* b) {
    asm volatile(
        "mma.sync.aligned.m16n8k16.row.col.f32.f16.f16.f32 "
        "{%0,%1,%2,%3}, {%4,%5,%6,%7}, {%8,%9}, {%0,%1,%2,%3};"
        : "+f"(c[0]), "+f"(c[1]), "+f"(c[2]), "+f"(c[3])
        : "r"(a[0]), "r"(a[1]), "r"(a[2]), "r"(a[3]), "r"(b[0]), "r"(b[1]));
}
// fp16-accumulator mma: C/D are 2 b32 regs (4 halfs)
__device__ __forceinline__ void mma_h16(uint32_t* c, const uint32_t* a, const uint32_t* b) {
    asm volatile(
        "mma.sync.aligned.m16n8k16.row.col.f16.f16.f16.f16 "
        "{%0,%1}, {%2,%3,%4,%5}, {%6,%7}, {%0,%1};"
        : "+r"(c[0]), "+r"(c[1])
        : "r"(a[0]), "r"(a[1]), "r"(a[2]), "r"(a[3]), "r"(b[0]), "r"(b[1]));
}
__device__ __forceinline__ uint32_t ex2_f16x2(uint32_t x) {
    uint32_t d;
    asm("ex2.approx.f16x2 %0, %1;" : "=r"(d) : "r"(x));
    return d;
}
__device__ __forceinline__ void cp16(uint32_t dst, const void* src) {
    asm volatile("cp.async.cg.shared.global [%0], [%1], 16;" :: "r"(dst), "l"(src));
}
__device__ __forceinline__ void cp_commit() { asm volatile("cp.async.commit_group;"); }
__device__ __forceinline__ void cp_wait0()  { asm volatile("cp.async.wait_group 0;"); }
__device__ __forceinline__ void cp_wait1()  { asm volatile("cp.async.wait_group 1;"); }
__device__ __forceinline__ void cp_wait2()  { asm volatile("cp.async.wait_group 2;"); }

__device__ __forceinline__ uint32_t packh(float a, float b) {
    __half2 t = __floats2half2_rn(a, b);
    return *reinterpret_cast<uint32_t*>(&t);
}

#define SW64(off)  ((off) ^ (((off) >> 3) & 0x30))
// Q scale includes log2(e) for exp2-domain softmax downstream.
#define QSCALE  (0.125f * 1.4426950408889634f)

// ============================================================================
// fused pre-pass: convert x, Wq|Wk|Wv (packed), Wo to fp16 in ONE launch.
// MLP=4: each thread handles 4 widely-spaced float4s (independent loads).
// ============================================================================
#define N4_X   (ROWS * DIM / 4)
#define N4_WQ  (DIM * DIM / 4)
#define N4_WK  (DIM * KVDIM / 4)
#define N4_WV  (DIM * KVDIM / 4)
#define N4_WO  (DIM * DIM / 4)
#define N4_TOT (N4_X + N4_WQ + N4_WK + N4_WV + N4_WO)   // 4718592
#define N4_Q   (N4_TOT / 4)                              // 1179648

__global__ __launch_bounds__(256) void conv_all(
    const float4* __restrict__ x,  const float4* __restrict__ Wq,
    const float4* __restrict__ Wk, const float4* __restrict__ Wv,
    const float4* __restrict__ Wo,
    __half* __restrict__ dx, __half* __restrict__ dqkv, __half* __restrict__ dwo)
{
    int idx = blockIdx.x * 256 + threadIdx.x;
    if (idx >= N4_Q) return;

    float4 v[4];
    __half* dptr[4];
    #pragma unroll
    for (int k = 0; k < 4; k++) {
        int i = idx + k * N4_Q;
        const float4* src;
        __half* dst;
        int li, N4, dstride, coloff;
        if (i < N4_X) {
            src = x;  dst = dx;  li = i;
            N4 = DIM / 4;  dstride = DIM;  coloff = 0;
        } else if (i < N4_X + N4_WQ) {
            src = Wq; dst = dqkv; li = i - N4_X;
            N4 = DIM / 4;  dstride = QKVN; coloff = 0;
        } else if (i < N4_X + N4_WQ + N4_WK) {
            src = Wk; dst = dqkv; li = i - (N4_X + N4_WQ);
            N4 = KVDIM / 4; dstride = QKVN; coloff = DIM;
        } else if (i < N4_X + N4_WQ + N4_WK + N4_WV) {
            src = Wv; dst = dqkv; li = i - (N4_X + N4_WQ + N4_WK);
            N4 = KVDIM / 4; dstride = QKVN; coloff = DIM + KVDIM;
        } else {
            src = Wo; dst = dwo; li = i - (N4_X + N4_WQ + N4_WK + N4_WV);
            N4 = DIM / 4;  dstride = DIM;  coloff = 0;
        }
        int row = li / N4, c4 = li % N4;
        dptr[k] = dst + (long)row * dstride + coloff + c4 * 4;
        v[k] = src[li];   // 4 independent loads in flight
    }
    #pragma unroll
    for (int k = 0; k < 4; k++) {
        uint2 hh;
        hh.x = packh(v[k].x, v[k].y);
        hh.y = packh(v[k].z, v[k].w);
        *reinterpret_cast<uint2*>(dptr[k]) = hh;
    }
}

// ============================================================================
// fp16 single-product GEMM: C = A * B.  K = 2048 fixed.
// Block tile 128x128, BK=32 (R13 shape), 128 threads (4 warps 2x2), warp 64x64.
// *** 4-stage cp.async pipeline, wait_group 2 *** (deeper prefetch: the stage
// consumed at iter kt was committed 3 iters ago -> wait nearly always free).
// smem 4 x 16896 = 67.6 KB; 2 CTAs/SM preserved.
// EPI: 0 = fp32 out0 ; 1 = fused QKV (q scaled fp16 / k fp16 / v fp16)
// ============================================================================
#define GK      2048
#define G_NK    (GK / 32)          // 64
#define G_AB    8192
#define G_BB    8704
#define G_ST    (G_AB + G_BB)      // 16896
#define G_SMEM  (4 * G_ST)         // 67584
#define GBSTR   136

template<int EPI>
__global__ __launch_bounds__(128, 2) void gemm_fp16(
    int Bstride,
    const __half* __restrict__ A,
    const __half* __restrict__ B,
    void* __restrict__ out0, void* __restrict__ out1, void* __restrict__ out2)
{
    extern __shared__ __align__(16) char gsm[];
    const uint32_t sbase = smem_u32(gsm);

    const int tid  = threadIdx.x;
    const int lane = tid & 31;
    const int warp = tid >> 5;        // 0..3
    const int wm   = warp >> 1;       // 0..1
    const int wn   = warp & 1;        // 0..1
    const long M0  = (long)blockIdx.y * 128;
    const long N0  = (long)blockIdx.x * 128;

    float c[4][8][4];
    #pragma unroll
    for (int i = 0; i < 4; i++)
        #pragma unroll
        for (int j = 0; j < 8; j++)
            #pragma unroll
            for (int e = 0; e < 4; e++) c[i][j][e] = 0.0f;

    auto loadStage = [&](int st, int k0) {
        uint32_t sA = sbase + st * G_ST;
        uint32_t sB = sA + G_AB;
        #pragma unroll
        for (int i = 0; i < 4; i++) {
            int ci = tid + i * 128;
            int row = ci >> 2, ch = ci & 3;
            uint32_t so = SW64((uint32_t)(row * 64 + ch * 16));
            long go = (M0 + row) * (long)GK + k0 + ch * 8;
            cp16(sA + so, A + go);
        }
        #pragma unroll
        for (int i = 0; i < 4; i++) {
            int ci = tid + i * 128;
            int row = ci >> 4, c8 = ci & 15;
            uint32_t so = (uint32_t)(row * GBSTR + c8 * 8) * 2;
            long go = (long)(k0 + row) * Bstride + N0 + c8 * 8;
            cp16(sB + so, B + go);
        }
    };

    loadStage(0, 0);
    cp_commit();
    loadStage(1, 32);
    cp_commit();
    loadStage(2, 64);
    cp_commit();

    #pragma unroll 1
    for (int kt = 0; kt < G_NK; kt++) {
        if (kt + 2 < G_NK)      cp_wait2();
        else if (kt + 1 < G_NK) cp_wait1();
        else                    cp_wait0();
        __syncthreads();
        if (kt + 3 < G_NK) {
            loadStage((kt + 3) & 3, (kt + 3) * 32);
            cp_commit();
        }

        const uint32_t sA = sbase + (kt & 3) * G_ST;
        const uint32_t sB = sA + G_AB;

        #pragma unroll
        for (int kk = 0; kk < 32; kk += 16) {
            uint32_t ah[4][4], bb[4][4];
            #pragma unroll
            for (int i = 0; i < 4; i++) {
                int row = wm * 64 + i * 16 + (lane & 15);
                int colb = (kk + ((lane >> 4) << 3)) * 2;
                uint32_t off = SW64((uint32_t)(row * 64 + colb));
                ldsm_x4(ah[i], sA + off);
            }
            #pragma unroll
            for (int jp = 0; jp < 4; jp++) {
                int row = kk + (lane & 15);
                int col = wn * 64 + jp * 16 + ((lane >> 4) << 3);
                uint32_t off = (uint32_t)(row * GBSTR + col) * 2;
                ldsm_x4t(bb[jp], sB + off);
            }
            #pragma unroll
            for (int i = 0; i < 4; i++)
                #pragma unroll
                for (int jp = 0; jp < 4; jp++) {
                    mma_h(c[i][2 * jp],     ah[i], bb[jp]);
                    mma_h(c[i][2 * jp + 1], ah[i], bb[jp] + 2);
                }
        }
    }

    // ---- epilogue ----
    float scale = 1.0f;
    __half* dsth = nullptr;
    long dstride = 0, col0 = 0;
    if (EPI == 1) {
        if (N0 < DIM)              { dsth = (__half*)out0; dstride = DIM;   col0 = N0;               scale = QSCALE; }
        else if (N0 < DIM + KVDIM) { dsth = (__half*)out1; dstride = KVDIM; col0 = N0 - DIM;         }
        else                       { dsth = (__half*)out2; dstride = KVDIM; col0 = N0 - DIM - KVDIM; }
    }

    #pragma unroll
    for (int i = 0; i < 4; i++) {
        long r0 = M0 + wm * 64 + i * 16 + (lane >> 2);
        #pragma unroll
        for (int j = 0; j < 8; j++) {
            long cc = wn * 64 + j * 8 + 2 * (lane & 3);
            float v0 = c[i][j][0] * scale, v1 = c[i][j][1] * scale;
            float v2 = c[i][j][2] * scale, v3 = c[i][j][3] * scale;
            if (EPI == 0) {
                float* C = (float*)out0;
                *reinterpret_cast<float2*>(&C[r0 * DIM + N0 + cc])       = make_float2(v0, v1);
                *reinterpret_cast<float2*>(&C[(r0 + 8) * DIM + N0 + cc]) = make_float2(v2, v3);
            } else {
                *reinterpret_cast<uint32_t*>(&dsth[r0 * dstride + col0 + cc])       = packh(v0, v1);
                *reinterpret_cast<uint32_t*>(&dsth[(r0 + 8) * dstride + col0 + cc]) = packh(v2, v3);
            }
        }
    }
}

// ============================================================================
// fp16 flash attention — fp16 S/P datapath (unchanged from R13).
// 4 warps, 32 q-rows/warp, KT=64, double-buffered cp.async, 2 CTAs/SM.
// ============================================================================
#define TSTR 72
#define Q_BYTES  (128 * TSTR * 2)              // 18432
#define KV_BYTES (64 * TSTR * 2)               //  9216
#define A_STAGE  (2 * KV_BYTES)
#define ATTN_SMEM (Q_BYTES + 2 * A_STAGE)      // 55296

__global__ __launch_bounds__(128, 2) void attn_fp16(
    const __half* __restrict__ Q_g,
    const __half* __restrict__ K_g,  const __half* __restrict__ V_g,
    __half* __restrict__ O_g)
{
    extern __shared__ __align__(16) char smp[];
    const uint32_t sb  = smem_u32(smp);
    const uint32_t sQ  = sb;
    const uint32_t sKV = sb + Q_BYTES;

    const int tid  = threadIdx.x;
    const int lane = tid & 31;
    const int warp = tid >> 5;
    const int qt = blockIdx.x, h = blockIdx.y, b = blockIdx.z;
    const int kvh = h >> 2;

    // ---- init V padding cols 64..71 = {1,0,...} for BOTH stages ----
    {
        int st = tid >> 6, row = tid & 63;
        char* p = smp + (size_t)(Q_BYTES + st * A_STAGE + KV_BYTES) +
                  (size_t)(row * TSTR + 64) * 2;
        *reinterpret_cast<uint4*>(p) = make_uint4(0x00003C00u, 0u, 0u, 0u);
    }

    auto loadKV = [&](int st, int kt) {
        uint32_t sK = sKV + st * A_STAGE;
        uint32_t sV = sK + KV_BYTES;
        #pragma unroll
        for (int i = 0; i < 4; i++) {
            int ci = tid + i * 128;
            int row = ci >> 3, c8 = ci & 7;
            uint32_t so = (uint32_t)(row * TSTR + c8 * 8) * 2;
            long go = (long)(b * SEQ + kt * 64 + row) * KVDIM + kvh * HD + c8 * 8;
            cp16(sK + so, K_g + go);
            cp16(sV + so, V_g + go);
        }
    };

    #pragma unroll
    for (int i = 0; i < 8; i++) {
        int ci = tid + i * 128;
        int row = ci >> 3, c8 = ci & 7;
        uint32_t so = (uint32_t)(row * TSTR + c8 * 8) * 2;
        long go = (long)(b * SEQ + qt * 128 + row) * DIM + h * HD + c8 * 8;
        cp16(sQ + so, Q_g + go);
    }
    loadKV(0, 0);
    cp_commit();
    cp_wait0();
    __syncthreads();

    uint32_t qh[2][4][4];
    #pragma unroll
    for (int rt = 0; rt < 2; rt++)
        #pragma unroll
        for (int t = 0; t < 4; t++) {
            int row = warp * 32 + rt * 16 + (lane & 15);
            int col = t * 16 + (lane >> 4) * 8;
            ldsm_x4(qh[rt][t], sQ + (uint32_t)(row * TSTR + col) * 2);
        }

    float o[2][8][4];
    #pragma unroll
    for (int rt = 0; rt < 2; rt++)
        #pragma unroll
        for (int j = 0; j < 8; j++)
            #pragma unroll
            for (int e = 0; e < 4; e++) o[rt][j][e] = 0.0f;
    float ol[2][4];
    #pragma unroll
    for (int rt = 0; rt < 2; rt++)
        #pragma unroll
        for (int e = 0; e < 4; e++) ol[rt][e] = 0.0f;

    for (int kt = 0; kt < SEQ / 64; kt++) {
        const int cur = kt & 1;
        if (kt + 1 < SEQ / 64) { loadKV(cur ^ 1, kt + 1); }
        cp_commit();

        const uint32_t sK = sKV + cur * A_STAGE;
        const uint32_t sV = sK + KV_BYTES;

        uint32_t s16[2][8][2];
        #pragma unroll
        for (int rt = 0; rt < 2; rt++)
            #pragma unroll
            for (int j = 0; j < 8; j++) { s16[rt][j][0] = 0u; s16[rt][j][1] = 0u; }

        const int l7 = lane & 7, g4 = lane >> 3;
        #pragma unroll
        for (int t = 0; t < 4; t++) {
            #pragma unroll
            for (int jp = 0; jp < 4; jp++) {
                uint32_t kb[4];
                int row = jp * 16 + ((g4 >> 1) << 3) + l7;
                int col = t * 16 + ((g4 & 1) << 3);
                ldsm_x4(kb, sK + (uint32_t)(row * TSTR + col) * 2);
                #pragma unroll
                for (int rt = 0; rt < 2; rt++) {
                    mma_h16(s16[rt][2 * jp],     qh[rt][t], kb);
                    mma_h16(s16[rt][2 * jp + 1], qh[rt][t], kb + 2);
                }
            }
        }

        #pragma unroll
        for (int rt = 0; rt < 2; rt++)
            #pragma unroll
            for (int j = 0; j < 8; j++) {
                s16[rt][j][0] = ex2_f16x2(s16[rt][j][0]);
                s16[rt][j][1] = ex2_f16x2(s16[rt][j][1]);
            }

        #pragma unroll
        for (int t = 0; t < 4; t++) {
            uint32_t ph[2][4];
            #pragma unroll
            for (int rt = 0; rt < 2; rt++) {
                ph[rt][0] = s16[rt][2 * t][0];
                ph[rt][1] = s16[rt][2 * t][1];
                ph[rt][2] = s16[rt][2 * t + 1][0];
                ph[rt][3] = s16[rt][2 * t + 1][1];
            }
            #pragma unroll
            for (int jp = 0; jp < 4; jp++) {
                uint32_t vb[4];
                int row = t * 16 + (lane & 15);
                int col = jp * 16 + ((lane >> 4) << 3);
                ldsm_x4t(vb, sV + (uint32_t)(row * TSTR + col) * 2);
                #pragma unroll
                for (int rt = 0; rt < 2; rt++) {
                    mma_h(o[rt][2 * jp],     ph[rt], vb);
                    mma_h(o[rt][2 * jp + 1], ph[rt], vb + 2);
                }
            }
            {
                uint32_t vb1[2];
                int row = t * 16 + (lane & 15);
                ldsm_x2t(vb1, sV + (uint32_t)(row * TSTR + 64) * 2);
                #pragma unroll
                for (int rt = 0; rt < 2; rt++)
                    mma_h(ol[rt], ph[rt], vb1);
            }
        }

        if (kt + 1 < SEQ / 64) cp_wait0();
        __syncthreads();
    }

    #pragma unroll
    for (int rt = 0; rt < 2; rt++) {
        float lv0 = __shfl_sync(0xffffffffu, ol[rt][0], lane & 0x1C);
        float lv1 = __shfl_sync(0xffffffffu, ol[rt][2], lane & 0x1C);
        const float il0 = 1.0f / lv0, il1 = 1.0f / lv1;
        const long base = (long)(b * SEQ + qt * 128 + warp * 32 + rt * 16 +
                                 (lane >> 2)) * DIM + h * HD;
        #pragma unroll
        for (int j = 0; j < 8; j++) {
            const int col = j * 8 + 2 * (lane & 3);
            *reinterpret_cast<uint32_t*>(&O_g[base + col]) =
                packh(o[rt][j][0] * il0, o[rt][j][1] * il0);
            *reinterpret_cast<uint32_t*>(&O_g[base + 8L * DIM + col]) =
                packh(o[rt][j][2] * il1, o[rt][j][3] * il1);
        }
    }
}

// ============================================================================
// kernel_launch
// ============================================================================
extern "C" void kernel_launch(void* const* d_in, const int* in_sizes, int n_in,
                              void* d_out, int out_size)
{
    const float* x  = (const float*)d_in[0];
    const float* Wq = (const float*)d_in[1];
    const float* Wk = (const float*)d_in[2];
    const float* Wv = (const float*)d_in[3];
    const float* Wo = (const float*)d_in[4];
    float* out = (float*)d_out;

    void *px, *pwqkv, *pwo, *pQ, *pK, *pV, *pO;
    cudaGetSymbolAddress(&px, g_x);
    cudaGetSymbolAddress(&pwqkv, g_Wqkv); cudaGetSymbolAddress(&pwo, g_Wo);
    cudaGetSymbolAddress(&pQ, g_Q);
    cudaGetSymbolAddress(&pK, g_K);       cudaGetSymbolAddress(&pV, g_V);
    cudaGetSymbolAddress(&pO, g_O);

    cudaFuncSetAttribute((const void*)gemm_fp16<0>,
                         cudaFuncAttributeMaxDynamicSharedMemorySize, G_SMEM);
    cudaFuncSetAttribute((const void*)gemm_fp16<1>,
                         cudaFuncAttributeMaxDynamicSharedMemorySize, G_SMEM);
    cudaFuncSetAttribute((const void*)attn_fp16,
                         cudaFuncAttributeMaxDynamicSharedMemorySize, ATTN_SMEM);

    // fused pre-pass (one launch, MLP=4)
    conv_all<<<(N4_Q + 255) / 256, 256>>>(
        (const float4*)x, (const float4*)Wq, (const float4*)Wk,
        (const float4*)Wv, (const float4*)Wo,
        (__half*)px, (__half*)pwqkv, (__half*)pwo);

    // fused QKV projection: [4096,2048] x [2048,3072]
    gemm_fp16<1><<<dim3(QKVN / 128, ROWS / 128), 128, G_SMEM>>>(
        QKVN, (__half*)px, (__half*)pwqkv, pQ, pK, pV);
    // attention -> fp16
    attn_fp16<<<dim3(SEQ / 128, NHEADS, BATCH), 128, ATTN_SMEM>>>(
        (const __half*)pQ, (const __half*)pK, (const __half*)pV, (__half*)pO);
    // out = O @ Wo -> fp32
    gemm_fp16<0><<<dim3(DIM / 128, ROWS / 128), 128, G_SMEM>>>(
        DIM, (__half*)pO, (__half*)pwo, out, nullptr, nullptr);
}